// round 7
// baseline (speedup 1.0000x reference)
#include <cuda_runtime.h>
#include <cstddef>
#include <cstdint>

#define BB 512
#define TT 200
#define SI 100
#define DI 68
#define HS 256
#define HD 128
#define NN 10000
#define DDIM 512   // 2*HD + HS

typedef unsigned long long ull;

// packed f32x2 helpers (sm_103a FFMA2 — only reachable via PTX)
#define FFMA2(D, A, B, C) \
    asm("fma.rn.f32x2 %0, %1, %2, %3;" : "=l"(D) : "l"(A), "l"(B), "l"(C))
#define PACKDUP(D, S) \
    asm("mov.b64 %0, {%1, %1};" : "=l"(D) : "r"(__float_as_uint(S)))
#define UNPACK2(LO, HI, V) \
    asm("mov.b64 {%0, %1}, %2;" : "=f"(LO), "=f"(HI) : "l"(V))

// ---------------- scratch (static device arrays; no runtime allocation) ----------------
__device__ float g_s[BB * HS];                 // static branch output [B,HS]
__device__ float g_xwf[BB * TT * HD];          // xw fwd (pre-activation input proj)
__device__ float g_xwb[BB * TT * HD];          // xw bwd
__device__ float g_dpf[4 * BB * TT];           // per-warp partial fwd routed dots
__device__ float g_dpb[4 * BB * TT];           // per-warp partial bwd routed dots
__device__ float g_cs[BB];                     // per-trial static dot + bias
__device__ float g_wdyn_t[DI * HD];            // w_dyn transposed [k][o]
__device__ float g_wihf_t[HD * HD];            // w_ih_f transposed [k][o]
__device__ float g_wihb_t[HD * HD];
__device__ float g_whhfp[64 * 256];            // Whh_f k-pair interleaved: [j][2c,2c+1] = W^T[2j..2j+1][c]
__device__ float g_whhbp[64 * 256];
__device__ float g_bxf[HD];                    // b_ih_f + b_hh_f
__device__ float g_bxb[HD];

// ---------------- prep: transposes + k-pair packing + bias folds ----------------
__global__ void prep_kernel(const float* __restrict__ w_dyn,
                            const float* __restrict__ w_ih_f,
                            const float* __restrict__ w_hh_f,
                            const float* __restrict__ w_ih_b,
                            const float* __restrict__ w_hh_b,
                            const float* __restrict__ b_ih_f,
                            const float* __restrict__ b_hh_f,
                            const float* __restrict__ b_ih_b,
                            const float* __restrict__ b_hh_b) {
    int idx = blockIdx.x * blockDim.x + threadIdx.x;
    if (idx < HD * HD) {
        int o = idx / HD, k = idx % HD;
        g_wihf_t[k * HD + o] = w_ih_f[idx];
        g_wihb_t[k * HD + o] = w_ih_b[idx];
    }
    if (idx < 64 * HD) {               // Whh k-pair packed layout
        int j = idx >> 7, c = idx & 127;     // Wt[k][c] = w_hh[c*HD + k]
        g_whhfp[j * 256 + 2 * c]     = w_hh_f[c * HD + 2 * j];
        g_whhfp[j * 256 + 2 * c + 1] = w_hh_f[c * HD + 2 * j + 1];
        g_whhbp[j * 256 + 2 * c]     = w_hh_b[c * HD + 2 * j];
        g_whhbp[j * 256 + 2 * c + 1] = w_hh_b[c * HD + 2 * j + 1];
    }
    if (idx < HD * DI) {               // w_dyn is [HD,DI] row-major
        int o = idx / DI, i = idx % DI;
        g_wdyn_t[i * HD + o] = w_dyn[idx];
    }
    if (idx < HD) {
        g_bxf[idx] = b_ih_f[idx] + b_hh_f[idx];
        g_bxb[idx] = b_ih_b[idx] + b_hh_b[idx];
    }
}

// ---------------- static branch: 2-layer MLP, one block per trial ----------------
__global__ void static_kernel(const float* __restrict__ xs,
                              const float* __restrict__ w1, const float* __restrict__ b1,
                              const float* __restrict__ w2, const float* __restrict__ b2) {
    int b = blockIdx.x;
    int j = threadIdx.x;                // 256 threads, one per hidden unit
    __shared__ float xsh[SI];
    __shared__ float s1[HS];
    if (j < SI) xsh[j] = xs[b * SI + j];
    __syncthreads();
    float acc = b1[j];
    #pragma unroll 4
    for (int i = 0; i < SI; i++) acc += xsh[i] * w1[j * SI + i];
    s1[j] = fmaxf(acc, 0.f);
    __syncthreads();
    acc = b2[j];
    #pragma unroll 4
    for (int i = 0; i < HS; i++) acc += s1[i] * w2[j * HS + i];
    g_s[b * HS + j] = fmaxf(acc, 0.f);
}

// ---------------- fused: d = relu(x_dyn @ Wdyn^T + b); xw_{f,b} = d @ Wih^T + bx ----------------
__global__ void __launch_bounds__(256) fused_gemm_kernel(const float* __restrict__ xd,
                                                         const float* __restrict__ bdyn) {
    __shared__ float xs[8][4 * DI];        // per-warp x rows (4 x 68)
    __shared__ float ds[8][4][HD];         // per-warp d rows (4 x 128)
    int w = threadIdx.x >> 5, lane = threadIdx.x & 31;
    size_t row0 = ((size_t)blockIdx.x * 8 + w) * 4;     // grid = 102400/32 = 3200

    const float* src = xd + row0 * DI;
    for (int i = lane; i < 4 * DI; i += 32) xs[w][i] = src[i];
    __syncwarp();

    // ---- stage 1: d tile (packed over col-pairs) ----
    {
        ulonglong2 bv = *(const ulonglong2*)&bdyn[4 * lane];
        ull a0p = bv.x, a0q = bv.y, a1p = bv.x, a1q = bv.y;
        ull a2p = bv.x, a2q = bv.y, a3p = bv.x, a3q = bv.y;
        #pragma unroll 4
        for (int k = 0; k < DI; k++) {
            ulonglong2 wv = *(const ulonglong2*)&g_wdyn_t[k * HD + 4 * lane];
            ull v0, v1, v2, v3;
            PACKDUP(v0, xs[w][0 * DI + k]);
            PACKDUP(v1, xs[w][1 * DI + k]);
            PACKDUP(v2, xs[w][2 * DI + k]);
            PACKDUP(v3, xs[w][3 * DI + k]);
            FFMA2(a0p, v0, wv.x, a0p); FFMA2(a0q, v0, wv.y, a0q);
            FFMA2(a1p, v1, wv.x, a1p); FFMA2(a1q, v1, wv.y, a1q);
            FFMA2(a2p, v2, wv.x, a2p); FFMA2(a2q, v2, wv.y, a2q);
            FFMA2(a3p, v3, wv.x, a3p); FFMA2(a3q, v3, wv.y, a3q);
        }
        float lo, hi;
        #define ST_RELU(r, P, Q) { \
            UNPACK2(lo, hi, P); \
            ds[w][r][4 * lane + 0] = fmaxf(lo, 0.f); \
            ds[w][r][4 * lane + 1] = fmaxf(hi, 0.f); \
            UNPACK2(lo, hi, Q); \
            ds[w][r][4 * lane + 2] = fmaxf(lo, 0.f); \
            ds[w][r][4 * lane + 3] = fmaxf(hi, 0.f); }
        ST_RELU(0, a0p, a0q)
        ST_RELU(1, a1p, a1q)
        ST_RELU(2, a2p, a2q)
        ST_RELU(3, a3p, a3q)
        #undef ST_RELU
    }
    __syncwarp();

    // ---- stage 2: dual GEMM over k=128 (packed over col-pairs) ----
    ulonglong2 bf2 = *(const ulonglong2*)&g_bxf[4 * lane];
    ulonglong2 bb2 = *(const ulonglong2*)&g_bxb[4 * lane];
    ull f0p = bf2.x, f0q = bf2.y, f1p = bf2.x, f1q = bf2.y;
    ull f2p = bf2.x, f2q = bf2.y, f3p = bf2.x, f3q = bf2.y;
    ull g0p = bb2.x, g0q = bb2.y, g1p = bb2.x, g1q = bb2.y;
    ull g2p = bb2.x, g2q = bb2.y, g3p = bb2.x, g3q = bb2.y;

    #pragma unroll 2
    for (int k = 0; k < HD; k += 4) {
        float4 d0 = *(const float4*)&ds[w][0][k];
        float4 d1 = *(const float4*)&ds[w][1][k];
        float4 d2 = *(const float4*)&ds[w][2][k];
        float4 d3 = *(const float4*)&ds[w][3][k];
        #pragma unroll
        for (int kk = 0; kk < 4; kk++) {
            ulonglong2 wf = *(const ulonglong2*)&g_wihf_t[(k + kk) * HD + 4 * lane];
            ulonglong2 wb = *(const ulonglong2*)&g_wihb_t[(k + kk) * HD + 4 * lane];
            float v0 = (kk == 0) ? d0.x : (kk == 1) ? d0.y : (kk == 2) ? d0.z : d0.w;
            float v1 = (kk == 0) ? d1.x : (kk == 1) ? d1.y : (kk == 2) ? d1.z : d1.w;
            float v2 = (kk == 0) ? d2.x : (kk == 1) ? d2.y : (kk == 2) ? d2.z : d2.w;
            float v3 = (kk == 0) ? d3.x : (kk == 1) ? d3.y : (kk == 2) ? d3.z : d3.w;
            ull p0, p1, p2, p3;
            PACKDUP(p0, v0); PACKDUP(p1, v1); PACKDUP(p2, v2); PACKDUP(p3, v3);
            FFMA2(f0p, p0, wf.x, f0p); FFMA2(f0q, p0, wf.y, f0q);
            FFMA2(f1p, p1, wf.x, f1p); FFMA2(f1q, p1, wf.y, f1q);
            FFMA2(f2p, p2, wf.x, f2p); FFMA2(f2q, p2, wf.y, f2q);
            FFMA2(f3p, p3, wf.x, f3p); FFMA2(f3q, p3, wf.y, f3q);
            FFMA2(g0p, p0, wb.x, g0p); FFMA2(g0q, p0, wb.y, g0q);
            FFMA2(g1p, p1, wb.x, g1p); FFMA2(g1q, p1, wb.y, g1q);
            FFMA2(g2p, p2, wb.x, g2p); FFMA2(g2q, p2, wb.y, g2q);
            FFMA2(g3p, p3, wb.x, g3p); FFMA2(g3q, p3, wb.y, g3q);
        }
    }

    size_t obase = row0 * HD + 4 * lane;
    *(ulonglong2*)&g_xwf[obase + 0 * HD] = make_ulonglong2(f0p, f0q);
    *(ulonglong2*)&g_xwf[obase + 1 * HD] = make_ulonglong2(f1p, f1q);
    *(ulonglong2*)&g_xwf[obase + 2 * HD] = make_ulonglong2(f2p, f2q);
    *(ulonglong2*)&g_xwf[obase + 3 * HD] = make_ulonglong2(f3p, f3q);
    *(ulonglong2*)&g_xwb[obase + 0 * HD] = make_ulonglong2(g0p, g0q);
    *(ulonglong2*)&g_xwb[obase + 1 * HD] = make_ulonglong2(g1p, g1q);
    *(ulonglong2*)&g_xwb[obase + 2 * HD] = make_ulonglong2(g2p, g2q);
    *(ulonglong2*)&g_xwb[obase + 3 * HD] = make_ulonglong2(g3p, g3q);
}

// ---------------- RNN scan: full-column-per-thread, 1 block = 1 sequence ----------------
// grid = 1024 (trial = b>>1, dir = b&1), 128 threads, up to 3 blocks/SM.
// Thread owns output column `tid` and holds the full W column (64 ull regs).
// Per step: 32 broadcast LDS.128 of h + 64 FFMA2 (4 acc chains) + relu + 1 STS.
// h double-buffered in smem -> exactly ONE __syncthreads per step.
// No cross-warp partial exchange at all. Routed dot fused (width-32 reduce).
__global__ void __launch_bounds__(128, 3) rnn_scan_kernel(const int* __restrict__ order,
                                                          const float* __restrict__ nw) {
    __shared__ float h_sm[2][HD];
    int tid = threadIdx.x;               // 0..127 = output column
    int w = tid >> 5, l = tid & 31;
    int dir = blockIdx.x & 1;
    int trial = blockIdx.x >> 1;
    const float* __restrict__ Wp = dir ? g_whhbp : g_whhfp;
    const float* __restrict__ xw = dir ? g_xwb : g_xwf;
    float* __restrict__ dotp = dir ? g_dpb : g_dpf;

    // cache this thread's full W column: 64 k-pairs (64 ull = 128 regs)
    ull Wc[64];
    #pragma unroll
    for (int j = 0; j < 64; j++)
        Wc[j] = *(const ull*)&Wp[j * 256 + 2 * tid];

    float wn_c = nw[(size_t)order[trial] * DDIM + HS + dir * HD + tid];

    h_sm[0][tid] = 0.f;
    const float* xw_t = xw + (size_t)trial * TT * HD + tid;
    size_t dbase = (size_t)w * (BB * TT) + (size_t)trial * TT;

    int t0 = dir ? (TT - 1) : 0;
    int dt = dir ? -1 : 1;
    float xv_next = xw_t[(size_t)t0 * HD];
    __syncthreads();

    for (int step = 0; step < TT; ++step) {
        int t = t0 + dt * step;
        float xv = xv_next;
        if (step + 1 < TT)
            xv_next = xw_t[(size_t)(t + dt) * HD];    // prefetch next step
        const float* hb = h_sm[step & 1];

        // 64 FFMA2 over k-pairs, 4 interleaved accumulator chains
        ull a0 = 0, a1 = 0, a2 = 0, a3 = 0;
        #pragma unroll
        for (int q = 0; q < 8; q++) {
            ulonglong2 hA = *(const ulonglong2*)&hb[16 * q];       // pairs 8q, 8q+1
            ulonglong2 hB = *(const ulonglong2*)&hb[16 * q + 4];   // pairs 8q+2, 8q+3
            ulonglong2 hC = *(const ulonglong2*)&hb[16 * q + 8];
            ulonglong2 hD = *(const ulonglong2*)&hb[16 * q + 12];
            FFMA2(a0, hA.x, Wc[8 * q + 0], a0);
            FFMA2(a1, hA.y, Wc[8 * q + 1], a1);
            FFMA2(a2, hB.x, Wc[8 * q + 2], a2);
            FFMA2(a3, hB.y, Wc[8 * q + 3], a3);
            FFMA2(a0, hC.x, Wc[8 * q + 4], a0);
            FFMA2(a1, hC.y, Wc[8 * q + 5], a1);
            FFMA2(a2, hD.x, Wc[8 * q + 6], a2);
            FFMA2(a3, hD.y, Wc[8 * q + 7], a3);
        }
        float lo0, hi0, lo1, hi1, lo2, hi2, lo3, hi3;
        UNPACK2(lo0, hi0, a0);
        UNPACK2(lo1, hi1, a1);
        UNPACK2(lo2, hi2, a2);
        UNPACK2(lo3, hi3, a3);
        float s = ((lo0 + hi0) + (lo1 + hi1)) + ((lo2 + hi2) + (lo3 + hi3));
        s = fmaxf(s + xv, 0.f);
        h_sm[(step & 1) ^ 1][tid] = s;       // write OTHER buffer: no read/write race

        // fused routed dot: per-warp partial (width-32 reduce), off critical path
        float dp = s * wn_c;
        #pragma unroll
        for (int off = 16; off > 0; off >>= 1)
            dp += __shfl_down_sync(0xffffffffu, dp, off);
        if (l == 0) dotp[dbase + t] = dp;

        __syncthreads();                     // single barrier per step
    }
}

// ---------------- c_s[b] = <s[b], Wn[:256]> + bn ----------------
__global__ void cs_kernel(const int* __restrict__ order,
                          const float* __restrict__ nw,
                          const float* __restrict__ nb) {
    int b = blockIdx.x;
    int tid = threadIdx.x;               // 256
    int n = order[b];
    float v = g_s[b * HS + tid] * nw[(size_t)n * DDIM + tid];
    #pragma unroll
    for (int s = 16; s > 0; s >>= 1) v += __shfl_down_sync(0xffffffffu, v, s);
    __shared__ float partial[8];
    if ((tid & 31) == 0) partial[tid >> 5] = v;
    __syncthreads();
    if (tid == 0) {
        float sum = 0.f;
        #pragma unroll
        for (int i = 0; i < 8; i++) sum += partial[i];
        g_cs[b] = sum + nb[n];
    }
}

// ---------------- out[b,t] = relu(cs[b] + sum of 8 per-warp dot partials) ----------------
__global__ void combine_kernel(float* __restrict__ out) {
    int i = blockIdx.x * 256 + threadIdx.x;    // 102400 total
    int b = i / TT;
    float s = g_cs[b];
    #pragma unroll
    for (int w = 0; w < 4; w++)
        s += g_dpf[w * (BB * TT) + i] + g_dpb[w * (BB * TT) + i];
    out[i] = fmaxf(s, 0.f);
}

// ---------------- launch ----------------
extern "C" void kernel_launch(void* const* d_in, const int* in_sizes, int n_in,
                              void* d_out, int out_size) {
    const float* x_static  = (const float*)d_in[0];
    const float* x_dynamic = (const float*)d_in[1];
    const int*   order     = (const int*)  d_in[2];
    const float* w_s1      = (const float*)d_in[3];
    const float* b_s1      = (const float*)d_in[4];
    const float* w_s2      = (const float*)d_in[5];
    const float* b_s2      = (const float*)d_in[6];
    const float* w_dyn     = (const float*)d_in[7];
    const float* b_dyn     = (const float*)d_in[8];
    const float* w_ih_f    = (const float*)d_in[9];
    const float* w_hh_f    = (const float*)d_in[10];
    const float* b_ih_f    = (const float*)d_in[11];
    const float* b_hh_f    = (const float*)d_in[12];
    const float* w_ih_b    = (const float*)d_in[13];
    const float* w_hh_b    = (const float*)d_in[14];
    const float* b_ih_b    = (const float*)d_in[15];
    const float* b_hh_b    = (const float*)d_in[16];
    const float* nw        = (const float*)d_in[17];
    const float* nb        = (const float*)d_in[18];
    float* out = (float*)d_out;

    prep_kernel<<<64, 256>>>(w_dyn, w_ih_f, w_hh_f, w_ih_b, w_hh_b,
                             b_ih_f, b_hh_f, b_ih_b, b_hh_b);
    static_kernel<<<BB, 256>>>(x_static, w_s1, b_s1, w_s2, b_s2);
    fused_gemm_kernel<<<BB * TT / 32, 256>>>(x_dynamic, b_dyn);
    rnn_scan_kernel<<<BB * 2, 128>>>(order, nw);
    cs_kernel<<<BB, 256>>>(order, nw, nb);
    combine_kernel<<<BB * TT / 256, 256>>>(out);
}

// round 8
// speedup vs baseline: 1.2608x; 1.2608x over previous
#include <cuda_runtime.h>
#include <cstddef>
#include <cstdint>

#define BB 512
#define TT 200
#define SI 100
#define DI 68
#define HS 256
#define HD 128
#define NN 10000
#define DDIM 512   // 2*HD + HS

typedef unsigned long long ull;

// packed f32x2 helpers (sm_103a FFMA2 — only reachable via PTX)
#define FFMA2(D, A, B, C) \
    asm("fma.rn.f32x2 %0, %1, %2, %3;" : "=l"(D) : "l"(A), "l"(B), "l"(C))
#define PACKDUP(D, S) \
    asm("mov.b64 %0, {%1, %1};" : "=l"(D) : "r"(__float_as_uint(S)))
#define UNPACK2(LO, HI, V) \
    asm("mov.b64 {%0, %1}, %2;" : "=f"(LO), "=f"(HI) : "l"(V))

// ---------------- scratch (static device arrays; no runtime allocation) ----------------
__device__ float g_s[BB * HS];                 // static branch output [B,HS]
__device__ float g_xwf[BB * TT * HD];          // xw fwd (pre-activation input proj)
__device__ float g_xwb[BB * TT * HD];          // xw bwd
__device__ float g_dotf[BB * TT];              // per-(b,t) fwd routed dot
__device__ float g_dotb[BB * TT];              // per-(b,t) bwd routed dot
__device__ float g_cs[BB];                     // per-trial static dot + bias
__device__ float g_wdyn_t[DI * HD];            // w_dyn transposed [k][o]
__device__ float g_wihf_t[HD * HD];            // w_ih_f transposed [k][o]
__device__ float g_wihb_t[HD * HD];
__device__ float g_whhfp[64 * 256];            // Whh_f k-pair interleaved
__device__ float g_whhbp[64 * 256];
__device__ float g_bxf[HD];                    // b_ih_f + b_hh_f
__device__ float g_bxb[HD];

// ---------------- prep: transposes + k-pair packing + bias folds ----------------
__global__ void prep_kernel(const float* __restrict__ w_dyn,
                            const float* __restrict__ w_ih_f,
                            const float* __restrict__ w_hh_f,
                            const float* __restrict__ w_ih_b,
                            const float* __restrict__ w_hh_b,
                            const float* __restrict__ b_ih_f,
                            const float* __restrict__ b_hh_f,
                            const float* __restrict__ b_ih_b,
                            const float* __restrict__ b_hh_b) {
    int idx = blockIdx.x * blockDim.x + threadIdx.x;
    if (idx < HD * HD) {
        int o = idx / HD, k = idx % HD;
        g_wihf_t[k * HD + o] = w_ih_f[idx];
        g_wihb_t[k * HD + o] = w_ih_b[idx];
    }
    if (idx < 64 * HD) {               // Whh k-pair packed layout
        int j = idx >> 7, c = idx & 127;     // Wt[k][c] = w_hh[c*HD + k]
        g_whhfp[j * 256 + 2 * c]     = w_hh_f[c * HD + 2 * j];
        g_whhfp[j * 256 + 2 * c + 1] = w_hh_f[c * HD + 2 * j + 1];
        g_whhbp[j * 256 + 2 * c]     = w_hh_b[c * HD + 2 * j];
        g_whhbp[j * 256 + 2 * c + 1] = w_hh_b[c * HD + 2 * j + 1];
    }
    if (idx < HD * DI) {               // w_dyn is [HD,DI] row-major
        int o = idx / DI, i = idx % DI;
        g_wdyn_t[i * HD + o] = w_dyn[idx];
    }
    if (idx < HD) {
        g_bxf[idx] = b_ih_f[idx] + b_hh_f[idx];
        g_bxb[idx] = b_ih_b[idx] + b_hh_b[idx];
    }
}

// ---------------- static branch: 2-layer MLP, one block per trial ----------------
__global__ void static_kernel(const float* __restrict__ xs,
                              const float* __restrict__ w1, const float* __restrict__ b1,
                              const float* __restrict__ w2, const float* __restrict__ b2) {
    int b = blockIdx.x;
    int j = threadIdx.x;                // 256 threads, one per hidden unit
    __shared__ float xsh[SI];
    __shared__ float s1[HS];
    if (j < SI) xsh[j] = xs[b * SI + j];
    __syncthreads();
    float acc = b1[j];
    #pragma unroll 4
    for (int i = 0; i < SI; i++) acc += xsh[i] * w1[j * SI + i];
    s1[j] = fmaxf(acc, 0.f);
    __syncthreads();
    acc = b2[j];
    #pragma unroll 4
    for (int i = 0; i < HS; i++) acc += s1[i] * w2[j * HS + i];
    g_s[b * HS + j] = fmaxf(acc, 0.f);
}

// ---------------- fused GEMM v2: 8 rows/warp, d pre-duplicated in smem ----------------
// 128 threads = 4 warps; warp handles 8 rows. Lane owns output cols 4l..4l+3.
// Stage 1 (dynproj) writes relu(d) into smem as (v,v) float2 pairs so stage 2's
// packed FFMA2 operand is a single broadcast LDS.64 (no PACKDUP in the hot loop).
__global__ void __launch_bounds__(128, 4) fused_gemm_kernel(const float* __restrict__ xd,
                                                            const float* __restrict__ bdyn) {
    __shared__ float  xs[4][8 * DI];        // 8.7 KB: raw x rows
    __shared__ float2 dsd[4][8][HD];        // 32 KB: d duplicated pairs
    int w = threadIdx.x >> 5, lane = threadIdx.x & 31;
    size_t row0 = ((size_t)blockIdx.x * 4 + w) * 8;     // grid = 102400/32 = 3200

    const float* src = xd + row0 * DI;
    for (int i = lane; i < 8 * DI; i += 32) xs[w][i] = src[i];
    __syncwarp();

    // ---- stage 1: d tile, 8 rows x 4 cols (packed over col-pairs) ----
    {
        ulonglong2 bv = *(const ulonglong2*)&bdyn[4 * lane];
        ull ap[8], aq[8];
        #pragma unroll
        for (int r = 0; r < 8; r++) { ap[r] = bv.x; aq[r] = bv.y; }

        #pragma unroll 2
        for (int k = 0; k < DI; k += 4) {
            ulonglong2 w0 = *(const ulonglong2*)&g_wdyn_t[(k + 0) * HD + 4 * lane];
            ulonglong2 w1 = *(const ulonglong2*)&g_wdyn_t[(k + 1) * HD + 4 * lane];
            ulonglong2 w2 = *(const ulonglong2*)&g_wdyn_t[(k + 2) * HD + 4 * lane];
            ulonglong2 w3 = *(const ulonglong2*)&g_wdyn_t[(k + 3) * HD + 4 * lane];
            #pragma unroll
            for (int r = 0; r < 8; r++) {
                float4 x4 = *(const float4*)&xs[w][r * DI + k];
                ull p0, p1, p2, p3;
                PACKDUP(p0, x4.x); PACKDUP(p1, x4.y); PACKDUP(p2, x4.z); PACKDUP(p3, x4.w);
                FFMA2(ap[r], p0, w0.x, ap[r]); FFMA2(aq[r], p0, w0.y, aq[r]);
                FFMA2(ap[r], p1, w1.x, ap[r]); FFMA2(aq[r], p1, w1.y, aq[r]);
                FFMA2(ap[r], p2, w2.x, ap[r]); FFMA2(aq[r], p2, w2.y, aq[r]);
                FFMA2(ap[r], p3, w3.x, ap[r]); FFMA2(aq[r], p3, w3.y, aq[r]);
            }
        }
        // relu + store duplicated pairs: dsd[w][r][col] = (v, v)
        #pragma unroll
        for (int r = 0; r < 8; r++) {
            float lo, hi;
            UNPACK2(lo, hi, ap[r]);
            float v0 = fmaxf(lo, 0.f), v1 = fmaxf(hi, 0.f);
            UNPACK2(lo, hi, aq[r]);
            float v2 = fmaxf(lo, 0.f), v3 = fmaxf(hi, 0.f);
            dsd[w][r][4 * lane + 0] = make_float2(v0, v0);
            dsd[w][r][4 * lane + 1] = make_float2(v1, v1);
            dsd[w][r][4 * lane + 2] = make_float2(v2, v2);
            dsd[w][r][4 * lane + 3] = make_float2(v3, v3);
        }
    }
    __syncwarp();

    // ---- stage 2: dual GEMM over k=128, 8 rows (no PACKDUP) ----
    ulonglong2 bf2 = *(const ulonglong2*)&g_bxf[4 * lane];
    ulonglong2 bb2 = *(const ulonglong2*)&g_bxb[4 * lane];
    ull fp[8], fq[8], gp[8], gq[8];
    #pragma unroll
    for (int r = 0; r < 8; r++) { fp[r] = bf2.x; fq[r] = bf2.y; gp[r] = bb2.x; gq[r] = bb2.y; }

    #pragma unroll 2
    for (int k = 0; k < HD; k++) {
        ulonglong2 wf = *(const ulonglong2*)&g_wihf_t[k * HD + 4 * lane];
        ulonglong2 wb = *(const ulonglong2*)&g_wihb_t[k * HD + 4 * lane];
        #pragma unroll
        for (int r = 0; r < 8; r++) {
            ull d2 = *(const ull*)&dsd[w][r][k];      // broadcast LDS.64, already (v,v)
            FFMA2(fp[r], d2, wf.x, fp[r]);
            FFMA2(fq[r], d2, wf.y, fq[r]);
            FFMA2(gp[r], d2, wb.x, gp[r]);
            FFMA2(gq[r], d2, wb.y, gq[r]);
        }
    }

    size_t obase = row0 * HD + 4 * lane;
    #pragma unroll
    for (int r = 0; r < 8; r++) {
        *(ulonglong2*)&g_xwf[obase + (size_t)r * HD] = make_ulonglong2(fp[r], fq[r]);
        *(ulonglong2*)&g_xwb[obase + (size_t)r * HD] = make_ulonglong2(gp[r], gq[r]);
    }
}

// ---------------- RNN scan + fused routed dot (R5 layout: best measured) ----------------
// grid = 256 blocks, 2 co-resident per SM. Block: dir = b&1, trials (b>>1)*4..+3.
// Warp w owns k-pairs [8w,8w+8); lane owns 4 output cols. W tile in 64 regs.
// pass2 slot: trial rt = tid>>6, cols 2rc..2rc+1 (rc = tid&63).
__global__ void __launch_bounds__(256, 2) rnn_scan_kernel(const int* __restrict__ order,
                                                          const float* __restrict__ nw) {
    __shared__ float h_sm[4][HD];           // 2 KB
    __shared__ float part[8][4][HD];        // 16 KB: [kslice][trial][col]
    __shared__ float wn_sm[4][HD];          // 2 KB: routed weights for this dir
    __shared__ float dsum[4][2];
    int tid = threadIdx.x;
    int w = tid >> 5, l = tid & 31;
    int dir = blockIdx.x & 1;
    int tbase = (blockIdx.x >> 1) * 4;
    const float* __restrict__ Wp = dir ? g_whhbp : g_whhfp;
    const float* __restrict__ xw = dir ? g_xwb : g_xwf;
    float* __restrict__ dot = dir ? g_dotb : g_dotf;

    // cache packed W tile: k-pairs 8w..8w+7, cols 4l..4l+3 (32 x f32x2 = 64 regs)
    ull Wa[8][4];
    #pragma unroll
    for (int jj = 0; jj < 8; jj++) {
        ulonglong2 p0 = *(const ulonglong2*)&Wp[(8 * w + jj) * 256 + 8 * l];
        ulonglong2 p1 = *(const ulonglong2*)&Wp[(8 * w + jj) * 256 + 8 * l + 4];
        Wa[jj][0] = p0.x; Wa[jj][1] = p0.y; Wa[jj][2] = p1.x; Wa[jj][3] = p1.y;
    }

    // load routed weights for 4 trials (2 floats per thread)
    {
        int tr = tid >> 6, c = (tid & 63) * 2;
        int n = order[tbase + tr];
        const float* wsrc = nw + (size_t)n * DDIM + HS + dir * HD + c;
        wn_sm[tr][c]     = wsrc[0];
        wn_sm[tr][c + 1] = wsrc[1];
    }

    // zero h (512 floats, 2 per thread)
    *(float2*)&((float*)h_sm)[2 * tid] = make_float2(0.f, 0.f);

    int rt = tid >> 6;
    int rc = tid & 63;
    const float* xw_rt = xw + (size_t)(tbase + rt) * TT * HD + 2 * rc;

    __syncthreads();
    float2 wn2 = *(const float2*)&wn_sm[rt][2 * rc];

    for (int step = 0; step < TT; ++step) {
        int t = dir ? (TT - 1 - step) : step;

        // prefetch xw for the reduction pass
        float2 xv = *(const float2*)&xw_rt[(size_t)t * HD];

        // ---- pass 1: partial GEMV over this warp's k-slice, per trial ----
        #pragma unroll
        for (int tr = 0; tr < 4; tr++) {
            ull a0 = 0, a1 = 0, a2 = 0, a3 = 0;
            #pragma unroll
            for (int q = 0; q < 4; q++) {
                ulonglong2 h4 = *(const ulonglong2*)&h_sm[tr][w * 16 + 4 * q];  // broadcast
                FFMA2(a0, h4.x, Wa[2 * q][0], a0); FFMA2(a0, h4.y, Wa[2 * q + 1][0], a0);
                FFMA2(a1, h4.x, Wa[2 * q][1], a1); FFMA2(a1, h4.y, Wa[2 * q + 1][1], a1);
                FFMA2(a2, h4.x, Wa[2 * q][2], a2); FFMA2(a2, h4.y, Wa[2 * q + 1][2], a2);
                FFMA2(a3, h4.x, Wa[2 * q][3], a3); FFMA2(a3, h4.y, Wa[2 * q + 1][3], a3);
            }
            float lo0, hi0, lo1, hi1, lo2, hi2, lo3, hi3;
            UNPACK2(lo0, hi0, a0);
            UNPACK2(lo1, hi1, a1);
            UNPACK2(lo2, hi2, a2);
            UNPACK2(lo3, hi3, a3);
            *(float4*)&part[w][tr][4 * l] =
                make_float4(lo0 + hi0, lo1 + hi1, lo2 + hi2, lo3 + hi3);
        }
        __syncthreads();   // h reads done; partials visible

        // ---- pass 2: reduce 8 k-slices for (rt, cols 2rc..2rc+1) ----
        float2 s = *(const float2*)&part[0][rt][2 * rc];
        #pragma unroll
        for (int ww = 1; ww < 8; ww++) {
            float2 p = *(const float2*)&part[ww][rt][2 * rc];
            s.x += p.x; s.y += p.y;
        }
        s.x = fmaxf(s.x + xv.x, 0.f);
        s.y = fmaxf(s.y + xv.y, 0.f);
        *(float2*)&h_sm[rt][2 * rc] = s;

        // fused routed dot: h . wn  (64 threads per trial = 2 warps)
        float dp = s.x * wn2.x + s.y * wn2.y;
        #pragma unroll
        for (int off = 16; off > 0; off >>= 1)
            dp += __shfl_down_sync(0xffffffffu, dp, off);
        if (l == 0) dsum[rt][(tid >> 5) & 1] = dp;
        __syncthreads();   // new h + dsum visible

        if (tid < 4)
            dot[(size_t)(tbase + tid) * TT + t] = dsum[tid][0] + dsum[tid][1];
    }
}

// ---------------- c_s[b] = <s[b], Wn[:256]> + bn ----------------
__global__ void cs_kernel(const int* __restrict__ order,
                          const float* __restrict__ nw,
                          const float* __restrict__ nb) {
    int b = blockIdx.x;
    int tid = threadIdx.x;               // 256
    int n = order[b];
    float v = g_s[b * HS + tid] * nw[(size_t)n * DDIM + tid];
    #pragma unroll
    for (int s = 16; s > 0; s >>= 1) v += __shfl_down_sync(0xffffffffu, v, s);
    __shared__ float partial[8];
    if ((tid & 31) == 0) partial[tid >> 5] = v;
    __syncthreads();
    if (tid == 0) {
        float sum = 0.f;
        #pragma unroll
        for (int i = 0; i < 8; i++) sum += partial[i];
        g_cs[b] = sum + nb[n];
    }
}

// ---------------- out[b,t] = relu(cs[b] + dotf[b,t] + dotb[b,t]) ----------------
__global__ void combine_kernel(float* __restrict__ out) {
    int i = blockIdx.x * 256 + threadIdx.x;    // 102400 total
    int b = i / TT;
    out[i] = fmaxf(g_cs[b] + g_dotf[i] + g_dotb[i], 0.f);
}

// ---------------- launch ----------------
extern "C" void kernel_launch(void* const* d_in, const int* in_sizes, int n_in,
                              void* d_out, int out_size) {
    const float* x_static  = (const float*)d_in[0];
    const float* x_dynamic = (const float*)d_in[1];
    const int*   order     = (const int*)  d_in[2];
    const float* w_s1      = (const float*)d_in[3];
    const float* b_s1      = (const float*)d_in[4];
    const float* w_s2      = (const float*)d_in[5];
    const float* b_s2      = (const float*)d_in[6];
    const float* w_dyn     = (const float*)d_in[7];
    const float* b_dyn     = (const float*)d_in[8];
    const float* w_ih_f    = (const float*)d_in[9];
    const float* w_hh_f    = (const float*)d_in[10];
    const float* b_ih_f    = (const float*)d_in[11];
    const float* b_hh_f    = (const float*)d_in[12];
    const float* w_ih_b    = (const float*)d_in[13];
    const float* w_hh_b    = (const float*)d_in[14];
    const float* b_ih_b    = (const float*)d_in[15];
    const float* b_hh_b    = (const float*)d_in[16];
    const float* nw        = (const float*)d_in[17];
    const float* nb        = (const float*)d_in[18];
    float* out = (float*)d_out;

    prep_kernel<<<64, 256>>>(w_dyn, w_ih_f, w_hh_f, w_ih_b, w_hh_b,
                             b_ih_f, b_hh_f, b_ih_b, b_hh_b);
    static_kernel<<<BB, 256>>>(x_static, w_s1, b_s1, w_s2, b_s2);
    fused_gemm_kernel<<<BB * TT / 32, 128>>>(x_dynamic, b_dyn);
    rnn_scan_kernel<<<256, 256>>>(order, nw);
    cs_kernel<<<BB, 256>>>(order, nw, nb);
    combine_kernel<<<BB * TT / 256, 256>>>(out);
}

// round 9
// speedup vs baseline: 1.6075x; 1.2750x over previous
#include <cuda_runtime.h>
#include <cstddef>
#include <cstdint>

#define BB 512
#define TT 200
#define SI 100
#define DI 68
#define HS 256
#define HD 128
#define NN 10000
#define DDIM 512   // 2*HD + HS

typedef unsigned long long ull;

// packed f32x2 helpers (sm_103a FFMA2 — only reachable via PTX)
#define FFMA2(D, A, B, C) \
    asm("fma.rn.f32x2 %0, %1, %2, %3;" : "=l"(D) : "l"(A), "l"(B), "l"(C))
#define PACKDUP(D, S) \
    asm("mov.b64 %0, {%1, %1};" : "=l"(D) : "r"(__float_as_uint(S)))
#define UNPACK2(LO, HI, V) \
    asm("mov.b64 {%0, %1}, %2;" : "=f"(LO), "=f"(HI) : "l"(V))

// ---------------- scratch (static device arrays; no runtime allocation) ----------------
__device__ float g_xwf[BB * TT * HD];          // xw fwd (pre-activation input proj)
__device__ float g_xwb[BB * TT * HD];          // xw bwd
__device__ float g_dotf[BB * TT];              // per-(b,t) fwd routed dot
__device__ float g_dotb[BB * TT];              // per-(b,t) bwd routed dot
__device__ float g_cs[BB];                     // per-trial static dot + bias
__device__ float g_wdyn_t[DI * HD];            // w_dyn transposed [k][o]
__device__ float g_wihf_t[HD * HD];            // w_ih_f transposed [k][o]
__device__ float g_wihb_t[HD * HD];
__device__ float g_whhfp[64 * 256];            // Whh_f k-pair interleaved
__device__ float g_whhbp[64 * 256];
__device__ float g_ws1t[SI * HS];              // w_s1 transposed [i][j]
__device__ float g_ws2t[HS * HS];              // w_s2 transposed [i][j]
__device__ float g_bxf[HD];                    // b_ih_f + b_hh_f
__device__ float g_bxb[HD];

// ---------------- prep: transposes + k-pair packing + bias folds ----------------
__global__ void prep_kernel(const float* __restrict__ w_dyn,
                            const float* __restrict__ w_ih_f,
                            const float* __restrict__ w_hh_f,
                            const float* __restrict__ w_ih_b,
                            const float* __restrict__ w_hh_b,
                            const float* __restrict__ b_ih_f,
                            const float* __restrict__ b_hh_f,
                            const float* __restrict__ b_ih_b,
                            const float* __restrict__ b_hh_b,
                            const float* __restrict__ w_s1,
                            const float* __restrict__ w_s2) {
    int idx = blockIdx.x * blockDim.x + threadIdx.x;   // 65536 threads
    if (idx < HD * HD) {
        int o = idx / HD, k = idx % HD;
        g_wihf_t[k * HD + o] = w_ih_f[idx];
        g_wihb_t[k * HD + o] = w_ih_b[idx];
    }
    if (idx < 64 * HD) {               // Whh k-pair packed layout
        int j = idx >> 7, c = idx & 127;     // Wt[k][c] = w_hh[c*HD + k]
        g_whhfp[j * 256 + 2 * c]     = w_hh_f[c * HD + 2 * j];
        g_whhfp[j * 256 + 2 * c + 1] = w_hh_f[c * HD + 2 * j + 1];
        g_whhbp[j * 256 + 2 * c]     = w_hh_b[c * HD + 2 * j];
        g_whhbp[j * 256 + 2 * c + 1] = w_hh_b[c * HD + 2 * j + 1];
    }
    if (idx < HD * DI) {               // w_dyn is [HD,DI] row-major
        int o = idx / DI, i = idx % DI;
        g_wdyn_t[i * HD + o] = w_dyn[idx];
    }
    if (idx < HS * SI) {               // w_s1 is [HS,SI] row-major
        int o = idx / SI, i = idx % SI;
        g_ws1t[i * HS + o] = w_s1[idx];
    }
    if (idx < HS * HS) {               // w_s2 is [HS,HS] row-major
        int o = idx / HS, i = idx % HS;
        g_ws2t[i * HS + o] = w_s2[idx];
    }
    if (idx < HD) {
        g_bxf[idx] = b_ih_f[idx] + b_hh_f[idx];
        g_bxb[idx] = b_ih_b[idx] + b_hh_b[idx];
    }
}

// ---------------- static branch + fused cs: coalesced weight reads ----------------
// One block per trial, 256 threads (one per hidden unit). Weights pre-transposed
// so warp loads are 1 wavefront each. Ends with the routed static dot -> g_cs.
__global__ void static_kernel(const float* __restrict__ xs,
                              const float* __restrict__ b1,
                              const float* __restrict__ b2,
                              const int* __restrict__ order,
                              const float* __restrict__ nw,
                              const float* __restrict__ nb) {
    int b = blockIdx.x;
    int j = threadIdx.x;                // 256 threads
    __shared__ float xsh[SI];
    __shared__ float s1[HS];
    __shared__ float partial[8];
    if (j < SI) xsh[j] = xs[b * SI + j];
    __syncthreads();
    float acc = b1[j];
    #pragma unroll 4
    for (int i = 0; i < SI; i++) acc += xsh[i] * g_ws1t[i * HS + j];   // coalesced
    s1[j] = fmaxf(acc, 0.f);
    __syncthreads();
    acc = b2[j];
    #pragma unroll 4
    for (int i = 0; i < HS; i++) acc += s1[i] * g_ws2t[i * HS + j];    // coalesced
    float sj = fmaxf(acc, 0.f);

    // fused cs: <s[b], Wn[:256]> + bn
    int n = order[b];
    float v = sj * nw[(size_t)n * DDIM + j];
    #pragma unroll
    for (int s = 16; s > 0; s >>= 1) v += __shfl_down_sync(0xffffffffu, v, s);
    if ((j & 31) == 0) partial[j >> 5] = v;
    __syncthreads();
    if (j == 0) {
        float sum = 0.f;
        #pragma unroll
        for (int i = 0; i < 8; i++) sum += partial[i];
        g_cs[b] = sum + nb[n];
    }
}

// ---------------- fused GEMM v2: 8 rows/warp, d pre-duplicated in smem ----------------
// 128 threads = 4 warps; warp handles 8 rows. Lane owns output cols 4l..4l+3.
// Stage 1 (dynproj) writes relu(d) into smem as (v,v) float2 pairs so stage 2's
// packed FFMA2 operand is a single broadcast LDS.64 (no PACKDUP in the hot loop).
__global__ void __launch_bounds__(128, 4) fused_gemm_kernel(const float* __restrict__ xd,
                                                            const float* __restrict__ bdyn) {
    __shared__ float  xs[4][8 * DI];        // 8.7 KB: raw x rows
    __shared__ float2 dsd[4][8][HD];        // 32 KB: d duplicated pairs
    int w = threadIdx.x >> 5, lane = threadIdx.x & 31;
    size_t row0 = ((size_t)blockIdx.x * 4 + w) * 8;     // grid = 102400/32 = 3200

    const float* src = xd + row0 * DI;
    for (int i = lane; i < 8 * DI; i += 32) xs[w][i] = src[i];
    __syncwarp();

    // ---- stage 1: d tile, 8 rows x 4 cols (packed over col-pairs) ----
    {
        ulonglong2 bv = *(const ulonglong2*)&bdyn[4 * lane];
        ull ap[8], aq[8];
        #pragma unroll
        for (int r = 0; r < 8; r++) { ap[r] = bv.x; aq[r] = bv.y; }

        #pragma unroll 2
        for (int k = 0; k < DI; k += 4) {
            ulonglong2 w0 = *(const ulonglong2*)&g_wdyn_t[(k + 0) * HD + 4 * lane];
            ulonglong2 w1 = *(const ulonglong2*)&g_wdyn_t[(k + 1) * HD + 4 * lane];
            ulonglong2 w2 = *(const ulonglong2*)&g_wdyn_t[(k + 2) * HD + 4 * lane];
            ulonglong2 w3 = *(const ulonglong2*)&g_wdyn_t[(k + 3) * HD + 4 * lane];
            #pragma unroll
            for (int r = 0; r < 8; r++) {
                float4 x4 = *(const float4*)&xs[w][r * DI + k];
                ull p0, p1, p2, p3;
                PACKDUP(p0, x4.x); PACKDUP(p1, x4.y); PACKDUP(p2, x4.z); PACKDUP(p3, x4.w);
                FFMA2(ap[r], p0, w0.x, ap[r]); FFMA2(aq[r], p0, w0.y, aq[r]);
                FFMA2(ap[r], p1, w1.x, ap[r]); FFMA2(aq[r], p1, w1.y, aq[r]);
                FFMA2(ap[r], p2, w2.x, ap[r]); FFMA2(aq[r], p2, w2.y, aq[r]);
                FFMA2(ap[r], p3, w3.x, ap[r]); FFMA2(aq[r], p3, w3.y, aq[r]);
            }
        }
        // relu + store duplicated pairs: dsd[w][r][col] = (v, v)
        #pragma unroll
        for (int r = 0; r < 8; r++) {
            float lo, hi;
            UNPACK2(lo, hi, ap[r]);
            float v0 = fmaxf(lo, 0.f), v1 = fmaxf(hi, 0.f);
            UNPACK2(lo, hi, aq[r]);
            float v2 = fmaxf(lo, 0.f), v3 = fmaxf(hi, 0.f);
            dsd[w][r][4 * lane + 0] = make_float2(v0, v0);
            dsd[w][r][4 * lane + 1] = make_float2(v1, v1);
            dsd[w][r][4 * lane + 2] = make_float2(v2, v2);
            dsd[w][r][4 * lane + 3] = make_float2(v3, v3);
        }
    }
    __syncwarp();

    // ---- stage 2: dual GEMM over k=128, 8 rows (no PACKDUP) ----
    ulonglong2 bf2 = *(const ulonglong2*)&g_bxf[4 * lane];
    ulonglong2 bb2 = *(const ulonglong2*)&g_bxb[4 * lane];
    ull fp[8], fq[8], gp[8], gq[8];
    #pragma unroll
    for (int r = 0; r < 8; r++) { fp[r] = bf2.x; fq[r] = bf2.y; gp[r] = bb2.x; gq[r] = bb2.y; }

    #pragma unroll 2
    for (int k = 0; k < HD; k++) {
        ulonglong2 wf = *(const ulonglong2*)&g_wihf_t[k * HD + 4 * lane];
        ulonglong2 wb = *(const ulonglong2*)&g_wihb_t[k * HD + 4 * lane];
        #pragma unroll
        for (int r = 0; r < 8; r++) {
            ull d2 = *(const ull*)&dsd[w][r][k];      // broadcast LDS.64, already (v,v)
            FFMA2(fp[r], d2, wf.x, fp[r]);
            FFMA2(fq[r], d2, wf.y, fq[r]);
            FFMA2(gp[r], d2, wb.x, gp[r]);
            FFMA2(gq[r], d2, wb.y, gq[r]);
        }
    }

    size_t obase = row0 * HD + 4 * lane;
    #pragma unroll
    for (int r = 0; r < 8; r++) {
        *(ulonglong2*)&g_xwf[obase + (size_t)r * HD] = make_ulonglong2(fp[r], fq[r]);
        *(ulonglong2*)&g_xwb[obase + (size_t)r * HD] = make_ulonglong2(gp[r], gq[r]);
    }
}

// ---------------- RNN scan + fused routed dot (R5 layout: best measured) ----------------
// grid = 256 blocks, 2 co-resident per SM. Block: dir = b&1, trials (b>>1)*4..+3.
// Warp w owns k-pairs [8w,8w+8); lane owns 4 output cols. W tile in 64 regs.
// pass2 slot: trial rt = tid>>6, cols 2rc..2rc+1 (rc = tid&63).
__global__ void __launch_bounds__(256, 2) rnn_scan_kernel(const int* __restrict__ order,
                                                          const float* __restrict__ nw) {
    __shared__ float h_sm[4][HD];           // 2 KB
    __shared__ float part[8][4][HD];        // 16 KB: [kslice][trial][col]
    __shared__ float wn_sm[4][HD];          // 2 KB: routed weights for this dir
    __shared__ float dsum[4][2];
    int tid = threadIdx.x;
    int w = tid >> 5, l = tid & 31;
    int dir = blockIdx.x & 1;
    int tbase = (blockIdx.x >> 1) * 4;
    const float* __restrict__ Wp = dir ? g_whhbp : g_whhfp;
    const float* __restrict__ xw = dir ? g_xwb : g_xwf;
    float* __restrict__ dot = dir ? g_dotb : g_dotf;

    // cache packed W tile: k-pairs 8w..8w+7, cols 4l..4l+3 (32 x f32x2 = 64 regs)
    ull Wa[8][4];
    #pragma unroll
    for (int jj = 0; jj < 8; jj++) {
        ulonglong2 p0 = *(const ulonglong2*)&Wp[(8 * w + jj) * 256 + 8 * l];
        ulonglong2 p1 = *(const ulonglong2*)&Wp[(8 * w + jj) * 256 + 8 * l + 4];
        Wa[jj][0] = p0.x; Wa[jj][1] = p0.y; Wa[jj][2] = p1.x; Wa[jj][3] = p1.y;
    }

    // load routed weights for 4 trials (2 floats per thread)
    {
        int tr = tid >> 6, c = (tid & 63) * 2;
        int n = order[tbase + tr];
        const float* wsrc = nw + (size_t)n * DDIM + HS + dir * HD + c;
        wn_sm[tr][c]     = wsrc[0];
        wn_sm[tr][c + 1] = wsrc[1];
    }

    // zero h (512 floats, 2 per thread)
    *(float2*)&((float*)h_sm)[2 * tid] = make_float2(0.f, 0.f);

    int rt = tid >> 6;
    int rc = tid & 63;
    const float* xw_rt = xw + (size_t)(tbase + rt) * TT * HD + 2 * rc;

    __syncthreads();
    float2 wn2 = *(const float2*)&wn_sm[rt][2 * rc];

    for (int step = 0; step < TT; ++step) {
        int t = dir ? (TT - 1 - step) : step;

        // prefetch xw for the reduction pass
        float2 xv = *(const float2*)&xw_rt[(size_t)t * HD];

        // ---- pass 1: partial GEMV over this warp's k-slice, per trial ----
        #pragma unroll
        for (int tr = 0; tr < 4; tr++) {
            ull a0 = 0, a1 = 0, a2 = 0, a3 = 0;
            #pragma unroll
            for (int q = 0; q < 4; q++) {
                ulonglong2 h4 = *(const ulonglong2*)&h_sm[tr][w * 16 + 4 * q];  // broadcast
                FFMA2(a0, h4.x, Wa[2 * q][0], a0); FFMA2(a0, h4.y, Wa[2 * q + 1][0], a0);
                FFMA2(a1, h4.x, Wa[2 * q][1], a1); FFMA2(a1, h4.y, Wa[2 * q + 1][1], a1);
                FFMA2(a2, h4.x, Wa[2 * q][2], a2); FFMA2(a2, h4.y, Wa[2 * q + 1][2], a2);
                FFMA2(a3, h4.x, Wa[2 * q][3], a3); FFMA2(a3, h4.y, Wa[2 * q + 1][3], a3);
            }
            float lo0, hi0, lo1, hi1, lo2, hi2, lo3, hi3;
            UNPACK2(lo0, hi0, a0);
            UNPACK2(lo1, hi1, a1);
            UNPACK2(lo2, hi2, a2);
            UNPACK2(lo3, hi3, a3);
            *(float4*)&part[w][tr][4 * l] =
                make_float4(lo0 + hi0, lo1 + hi1, lo2 + hi2, lo3 + hi3);
        }
        __syncthreads();   // h reads done; partials visible

        // ---- pass 2: reduce 8 k-slices for (rt, cols 2rc..2rc+1) ----
        float2 s = *(const float2*)&part[0][rt][2 * rc];
        #pragma unroll
        for (int ww = 1; ww < 8; ww++) {
            float2 p = *(const float2*)&part[ww][rt][2 * rc];
            s.x += p.x; s.y += p.y;
        }
        s.x = fmaxf(s.x + xv.x, 0.f);
        s.y = fmaxf(s.y + xv.y, 0.f);
        *(float2*)&h_sm[rt][2 * rc] = s;

        // fused routed dot: h . wn  (64 threads per trial = 2 warps)
        float dp = s.x * wn2.x + s.y * wn2.y;
        #pragma unroll
        for (int off = 16; off > 0; off >>= 1)
            dp += __shfl_down_sync(0xffffffffu, dp, off);
        if (l == 0) dsum[rt][(tid >> 5) & 1] = dp;
        __syncthreads();   // new h + dsum visible

        if (tid < 4)
            dot[(size_t)(tbase + tid) * TT + t] = dsum[tid][0] + dsum[tid][1];
    }
}

// ---------------- out[b,t] = relu(cs[b] + dotf[b,t] + dotb[b,t]) ----------------
__global__ void combine_kernel(float* __restrict__ out) {
    int i = blockIdx.x * 256 + threadIdx.x;    // 102400 total
    int b = i / TT;
    out[i] = fmaxf(g_cs[b] + g_dotf[i] + g_dotb[i], 0.f);
}

// ---------------- launch ----------------
extern "C" void kernel_launch(void* const* d_in, const int* in_sizes, int n_in,
                              void* d_out, int out_size) {
    const float* x_static  = (const float*)d_in[0];
    const float* x_dynamic = (const float*)d_in[1];
    const int*   order     = (const int*)  d_in[2];
    const float* w_s1      = (const float*)d_in[3];
    const float* b_s1      = (const float*)d_in[4];
    const float* w_s2      = (const float*)d_in[5];
    const float* b_s2      = (const float*)d_in[6];
    const float* w_dyn     = (const float*)d_in[7];
    const float* b_dyn     = (const float*)d_in[8];
    const float* w_ih_f    = (const float*)d_in[9];
    const float* w_hh_f    = (const float*)d_in[10];
    const float* b_ih_f    = (const float*)d_in[11];
    const float* b_hh_f    = (const float*)d_in[12];
    const float* w_ih_b    = (const float*)d_in[13];
    const float* w_hh_b    = (const float*)d_in[14];
    const float* b_ih_b    = (const float*)d_in[15];
    const float* b_hh_b    = (const float*)d_in[16];
    const float* nw        = (const float*)d_in[17];
    const float* nb        = (const float*)d_in[18];
    float* out = (float*)d_out;

    prep_kernel<<<256, 256>>>(w_dyn, w_ih_f, w_hh_f, w_ih_b, w_hh_b,
                              b_ih_f, b_hh_f, b_ih_b, b_hh_b, w_s1, w_s2);
    static_kernel<<<BB, 256>>>(x_static, b_s1, b_s2, order, nw, nb);
    fused_gemm_kernel<<<BB * TT / 32, 128>>>(x_dynamic, b_dyn);
    rnn_scan_kernel<<<256, 256>>>(order, nw);
    combine_kernel<<<BB * TT / 256, 256>>>(out);
}